// round 15
// baseline (speedup 1.0000x reference)
#include <cuda_runtime.h>
#include <cstdint>

#define NN 512
#define DD 256
#define MARGIN 0.2f
#define NMAT 136          // triangular 32x32 tiles
#define NZERO 4096        // zero-fill blocks total (64 rows each)
#define NZ_A1 3072        // zero blocks in kernelA1 (anchors 0..383)
#define NZ_A2 (NZERO - NZ_A1)

// Scratch (device global, no allocation)
__device__ float g_mat[NN * NN];

// ---------------------------------------------------------------------------
// Packed f32x2 helpers (Blackwell). Negation via exact *-1 / fma preserves
// the TwoSum algebra.
// ---------------------------------------------------------------------------
__device__ __forceinline__ uint64_t pk2(float lo, float hi) {
    uint64_t d; asm("mov.b64 %0, {%1,%2};" : "=l"(d) : "f"(lo), "f"(hi)); return d;
}
__device__ __forceinline__ void upk2(uint64_t v, float& lo, float& hi) {
    asm("mov.b64 {%0,%1}, %2;" : "=f"(lo), "=f"(hi) : "l"(v));
}
__device__ __forceinline__ uint64_t mul2(uint64_t a, uint64_t b) {
    uint64_t d; asm("mul.rn.f32x2 %0, %1, %2;" : "=l"(d) : "l"(a), "l"(b)); return d;
}
__device__ __forceinline__ uint64_t add2(uint64_t a, uint64_t b) {
    uint64_t d; asm("add.rn.f32x2 %0, %1, %2;" : "=l"(d) : "l"(a), "l"(b)); return d;
}
__device__ __forceinline__ uint64_t fma2(uint64_t a, uint64_t b, uint64_t c) {
    uint64_t d; asm("fma.rn.f32x2 %0, %1, %2, %3;" : "=l"(d) : "l"(a), "l"(b), "l"(c)); return d;
}
#define NEG1_2 0xBF800000BF800000ULL
__device__ __forceinline__ uint64_t neg2(uint64_t x) { return mul2(x, NEG1_2); }
__device__ __forceinline__ uint64_t sub2(uint64_t a, uint64_t b) { return fma2(b, NEG1_2, a); }

// Compensated accumulate of product a*b into (S, C): Dot2 (Ogita-Rump-Oishi).
__device__ __forceinline__ void dot2_step(uint64_t a, uint64_t b,
                                          uint64_t& S, uint64_t& C) {
    uint64_t p  = mul2(a, b);
    uint64_t e  = fma2(a, b, neg2(p));   // exact product error
    uint64_t t  = add2(S, p);            // TwoSum(S, p)
    uint64_t bp = sub2(t, S);
    uint64_t d1 = sub2(S, sub2(t, bp));
    uint64_t d2 = sub2(p, bp);
    C = add2(C, add2(e, add2(d1, d2)));
    S = t;
}

// Scalar compensated helpers for row norms (identical rounding since R3)
__device__ __forceinline__ void sq_step(float v, float& s, float& c) {
    float p = __fmul_rn(v, v);
    float e = __fmaf_rn(v, v, -p);
    float t = __fadd_rn(s, p);
    float bp = __fsub_rn(t, s);
    float err = __fadd_rn(__fsub_rn(s, __fsub_rn(t, bp)), __fsub_rn(p, bp));
    c = __fadd_rn(c, __fadd_rn(err, e));
    s = t;
}
__device__ __forceinline__ void cs_merge(float& s, float& c, float s2, float c2) {
    float t = __fadd_rn(s, s2);
    float bp = __fsub_rn(t, s);
    float err = __fadd_rn(__fsub_rn(s, __fsub_rn(t, bp)), __fsub_rn(s2, bp));
    c = __fadd_rn(__fadd_rn(c, c2), err);
    s = t;
}

// ---------------------------------------------------------------------------
// mat tile (verbatim values since R3): row norms + compensated fp32x2 Gram ->
// distance matrix, 32x32 triangular tile per block, writes (m,n) + (n,m).
// ---------------------------------------------------------------------------
__device__ void mat_tile(const float* __restrict__ emb, int z, int tid) {
    __shared__ float As[16][33];
    __shared__ float Bs2[16][34];   // paired: [kk][2*tx + (0|1)] = rows tx, tx+16
    __shared__ float s_sq[64];      // [0:32)=A rows, [32:64)=B rows

    int bj = (int)((sqrtf(8.0f * (float)z + 1.0f) - 1.0f) * 0.5f);
    while ((bj + 1) * (bj + 2) / 2 <= z) bj++;
    while (bj * (bj + 1) / 2 > z) bj--;
    int bi = z - bj * (bj + 1) / 2;

    int m0 = bi * 32, n0 = bj * 32;
    int warp = tid >> 5, lane = tid & 31;
    int tx = tid & 15, ty = tid >> 4;

    #pragma unroll
    for (int r = 0; r < 8; r++) {
        int rl = warp * 8 + r;                       // 0..63
        int grow = (rl < 32) ? (m0 + rl) : (n0 + rl - 32);
        const float4* r4 = (const float4*)(emb + grow * DD);
        float4 x = r4[lane];
        float4 y = r4[lane + 32];
        float s = 0.0f, c = 0.0f;
        sq_step(x.x, s, c); sq_step(x.y, s, c); sq_step(x.z, s, c); sq_step(x.w, s, c);
        sq_step(y.x, s, c); sq_step(y.y, s, c); sq_step(y.z, s, c); sq_step(y.w, s, c);
        #pragma unroll
        for (int off = 16; off > 0; off >>= 1) {
            float s2 = __shfl_xor_sync(0xffffffffu, s, off);
            float c2 = __shfl_xor_sync(0xffffffffu, c, off);
            cs_merge(s, c, s2, c2);
        }
        if (lane == 0) s_sq[rl] = __fadd_rn(s, c);
    }
    __syncthreads();

    uint64_t S0 = 0, C0 = 0, S1 = 0, C1 = 0;

    for (int k0 = 0; k0 < DD; k0 += 16) {
        #pragma unroll
        for (int q = 0; q < 2; q++) {
            int idx = tid + q * 256;
            int r = idx >> 4, kk = idx & 15;
            As[kk][r] = emb[(m0 + r) * DD + k0 + kk];
            Bs2[kk][((r & 15) << 1) | (r >> 4)] = emb[(n0 + r) * DD + k0 + kk];
        }
        __syncthreads();
        #pragma unroll
        for (int kk = 0; kk < 16; kk++) {
            uint64_t b2 = *(const uint64_t*)&Bs2[kk][2 * tx];   // rows (tx, tx+16)
            float a0 = As[kk][ty];
            float a1 = As[kk][ty + 16];
            dot2_step(pk2(a0, a0), b2, S0, C0);
            dot2_step(pk2(a1, a1), b2, S1, C1);
        }
        __syncthreads();
    }

    float d00, d01, d10, d11;
    upk2(add2(S0, C0), d00, d01);
    upk2(add2(S1, C1), d10, d11);

    float dots[2][2] = {{d00, d01}, {d10, d11}};
    #pragma unroll
    for (int i = 0; i < 2; i++) {
        int ml = ty + 16 * i;
        int m = m0 + ml;
        float sm = s_sq[ml];
        #pragma unroll
        for (int j = 0; j < 2; j++) {
            int nl = tx + 16 * j;
            int n = n0 + nl;
            // ref order: (sq[a] + sq[n]) - 2*dot, then clamp — no FMA fusion
            float v = fmaxf(__fsub_rn(__fadd_rn(sm, s_sq[32 + nl]),
                                      __fmul_rn(2.0f, dots[i][j])), 0.0f);
            g_mat[m * NN + n] = v;
            g_mat[n * NN + m] = v;
        }
    }
}

// ---------------------------------------------------------------------------
// zero chunk (verbatim R13 zero path): zero-fill the invalid (a,p) rows of a
// 64-row chunk.
// ---------------------------------------------------------------------------
__device__ __forceinline__ void zero_chunk(const int* __restrict__ lw,
                                           float4* __restrict__ out,
                                           int zb, int tid) {
    __shared__ int s_not64;
    int a = zb >> 3;                     // 8 blocks per anchor
    int p0 = (zb & 7) << 6;              // 64-row chunk

    if (tid == 0) s_not64 = 0;
    __syncthreads();
    // Probe words [1,3,...,511]: within 2KB, valid for both label layouts.
    if (lw[2 * tid + 1] != 0) s_not64 = 1;
    __syncthreads();
    bool is64 = (s_not64 == 0);
    int la = is64 ? lw[2 * a] : lw[a];

    int warp = tid >> 5, lane = tid & 31;
    float4 zv = make_float4(0.0f, 0.0f, 0.0f, 0.0f);

    #pragma unroll
    for (int i = 0; i < 8; i++) {
        int p = p0 + warp * 8 + i;
        int lp = is64 ? lw[2 * p] : lw[p];
        bool valid = (lp == la) && (p != a);
        if (!valid) {
            float4* orow = out + ((size_t)a * NN + p) * (NN / 4);
            #pragma unroll
            for (int q = 0; q < 4; q++)
                __stcs(&orow[q * 32 + lane], zv);
        }
    }
}

// ---------------------------------------------------------------------------
// Kernel A1: mat tiles (bids 0..135) + first 3072 zero chunks (anchors 0-383).
// ---------------------------------------------------------------------------
__global__ void __launch_bounds__(256) kernelA1(const float* __restrict__ emb,
                                                const int* __restrict__ lw,
                                                float4* __restrict__ out) {
    int tid = threadIdx.x;
    if (blockIdx.x < NMAT) {
        mat_tile(emb, blockIdx.x, tid);
        return;
    }
    zero_chunk(lw, out, blockIdx.x - NMAT, tid);
}

// ---------------------------------------------------------------------------
// Kernel A2: remaining 1024 zero chunks (anchors 384-511). Runs concurrent
// with kernelB (disjoint output rows: invalid vs valid).
// ---------------------------------------------------------------------------
__global__ void __launch_bounds__(256) kernelA2(const int* __restrict__ lw,
                                                float4* __restrict__ out) {
    zero_chunk(lw, out, blockIdx.x + NZ_A1, threadIdx.x);
}

// ---------------------------------------------------------------------------
// Kernel B (slim): valid rows only, one block per anchor. All global loads
// (label words + both g_mat row halves) issued in one parallel round; the
// is64 probe is derived from the already-loaded words. Compacts valid p's
// with their threshold values; writer loop does no global loads.
// Values bit-identical to R13/R14.
// ---------------------------------------------------------------------------
__global__ void __launch_bounds__(256) kernelB(const int* __restrict__ lw,
                                               float4* __restrict__ out) {
    __shared__ __align__(16) float s_key[NN];
    __shared__ int   s_plist[128];
    __shared__ float s_pval[128];
    __shared__ int s_cnt;

    int a = blockIdx.x;
    int tid = threadIdx.x;

    if (tid == 0) s_cnt = 0;

    // one parallel global round trip: words [0,512) + this anchor's mat row
    int w0 = lw[tid];
    int w1 = lw[tid + 256];
    float m0 = __ldcg(&g_mat[a * NN + tid]);
    float m1 = __ldcg(&g_mat[a * NN + tid + 256]);

    // probe: any odd word in [0,512) nonzero -> int32 layout.
    // thread tid holds words tid and tid+256 (both odd iff tid is odd).
    bool is64 = !__syncthreads_or((tid & 1) && ((w0 | w1) != 0));

    int la, ln0, ln1;
    if (!is64) {
        la = lw[a];            // L1/L2 hit (just loaded by this block)
        ln0 = w0;
        ln1 = w1;
    } else {
        // int64 layout: low words at even indices (buffer is 4KB in this case)
        la = lw[2 * a];
        ln0 = lw[2 * tid];
        ln1 = lw[2 * (tid + 256)];
    }

    const float INF = __int_as_float(0x7f800000);
    {
        int n = tid;
        bool same = (ln0 == la);
        s_key[n] = same ? INF : m0;                   // diffs gate
        if (same && n != a) {                         // sames gate -> compact
            int ix = atomicAdd(&s_cnt, 1);
            s_plist[ix] = n;
            s_pval[ix] = m0;
        }
    }
    {
        int n = tid + 256;
        bool same = (ln1 == la);
        s_key[n] = same ? INF : m1;
        if (same && n != a) {
            int ix = atomicAdd(&s_cnt, 1);
            s_plist[ix] = n;
            s_pval[ix] = m1;
        }
    }
    __syncthreads();

    int cnt = s_cnt;
    int warp = tid >> 5, lane = tid & 31;
    const float4* k4 = (const float4*)s_key;

    for (int i = warp; i < cnt; i += 8) {
        int p = s_plist[i];
        float t = s_pval[i];                          // same float as always
        float4* orow = out + ((size_t)a * NN + p) * (NN / 4);
        #pragma unroll
        for (int q = 0; q < 4; q++) {
            float4 f = k4[q * 32 + lane];
            float4 r;
            // ref: (mat[a,n] - mat[a,p]) <= MARGIN, fp32, no fusion.
            r.x = (__fsub_rn(f.x, t) <= MARGIN) ? 1.0f : 0.0f;
            r.y = (__fsub_rn(f.y, t) <= MARGIN) ? 1.0f : 0.0f;
            r.z = (__fsub_rn(f.z, t) <= MARGIN) ? 1.0f : 0.0f;
            r.w = (__fsub_rn(f.w, t) <= MARGIN) ? 1.0f : 0.0f;
            __stcs(&orow[q * 32 + lane], r);
        }
    }
}

// ---------------------------------------------------------------------------
// Side stream + fork/join events, created once at static init (host-side
// objects only, no device memory). Same capture pattern as R11/R12 (proven
// to capture and execute concurrently in-graph).
// ---------------------------------------------------------------------------
namespace {
struct SideStream {
    cudaStream_t s2 = nullptr;
    cudaEvent_t fork = nullptr, join = nullptr;
    SideStream() {
        cudaStreamCreateWithFlags(&s2, cudaStreamNonBlocking);
        cudaEventCreateWithFlags(&fork, cudaEventDisableTiming);
        cudaEventCreateWithFlags(&join, cudaEventDisableTiming);
    }
};
SideStream g_ss;
}

extern "C" void kernel_launch(void* const* d_in, const int* in_sizes, int n_in,
                              void* d_out, int out_size) {
    const float* emb = (const float*)d_in[0];
    const int* labels = (const int*)d_in[1];
    (void)in_sizes; (void)n_in; (void)out_size;

    // A1: mat (wave 1) + 373MB of zero stores. g_mat is complete when A1 ends.
    kernelA1<<<NMAT + NZ_A1, 256>>>(emb, labels, (float4*)d_out);

    // fork: kernelB depends only on mat (inside A1)
    cudaEventRecord(g_ss.fork, 0);
    cudaStreamWaitEvent(g_ss.s2, g_ss.fork, 0);
    kernelB<<<NN, 256, 0, g_ss.s2>>>(labels, (float4*)d_out);
    cudaEventRecord(g_ss.join, g_ss.s2);

    // A2: remaining 124MB of zero stores, concurrent with kernelB
    kernelA2<<<NZ_A2, 256>>>(labels, (float4*)d_out);

    // join: harness waits for both branches
    cudaStreamWaitEvent((cudaStream_t)0, g_ss.join, 0);
}

// round 16
// speedup vs baseline: 1.0027x; 1.0027x over previous
#include <cuda_runtime.h>
#include <cstdint>

#define NN 512
#define DD 256
#define MARGIN 0.2f
#define NMAT 136          // triangular 32x32 tiles
#define NZERO 4096        // zero-fill blocks (64 rows each)
#define NBLK (NMAT + NZERO)

// Scratch (device globals, no allocation)
__device__ float g_mat[NN * NN];
__device__ unsigned g_done;   // mat tiles completed (reset by reset_kernel)

// ---------------------------------------------------------------------------
// Packed f32x2 helpers (Blackwell). Negation via exact *-1 / fma preserves
// the TwoSum algebra.
// ---------------------------------------------------------------------------
__device__ __forceinline__ uint64_t pk2(float lo, float hi) {
    uint64_t d; asm("mov.b64 %0, {%1,%2};" : "=l"(d) : "f"(lo), "f"(hi)); return d;
}
__device__ __forceinline__ void upk2(uint64_t v, float& lo, float& hi) {
    asm("mov.b64 {%0,%1}, %2;" : "=f"(lo), "=f"(hi) : "l"(v));
}
__device__ __forceinline__ uint64_t mul2(uint64_t a, uint64_t b) {
    uint64_t d; asm("mul.rn.f32x2 %0, %1, %2;" : "=l"(d) : "l"(a), "l"(b)); return d;
}
__device__ __forceinline__ uint64_t add2(uint64_t a, uint64_t b) {
    uint64_t d; asm("add.rn.f32x2 %0, %1, %2;" : "=l"(d) : "l"(a), "l"(b)); return d;
}
__device__ __forceinline__ uint64_t fma2(uint64_t a, uint64_t b, uint64_t c) {
    uint64_t d; asm("fma.rn.f32x2 %0, %1, %2, %3;" : "=l"(d) : "l"(a), "l"(b), "l"(c)); return d;
}
#define NEG1_2 0xBF800000BF800000ULL
__device__ __forceinline__ uint64_t neg2(uint64_t x) { return mul2(x, NEG1_2); }
__device__ __forceinline__ uint64_t sub2(uint64_t a, uint64_t b) { return fma2(b, NEG1_2, a); }

// Compensated accumulate of product a*b into (S, C): Dot2 (Ogita-Rump-Oishi).
__device__ __forceinline__ void dot2_step(uint64_t a, uint64_t b,
                                          uint64_t& S, uint64_t& C) {
    uint64_t p  = mul2(a, b);
    uint64_t e  = fma2(a, b, neg2(p));   // exact product error
    uint64_t t  = add2(S, p);            // TwoSum(S, p)
    uint64_t bp = sub2(t, S);
    uint64_t d1 = sub2(S, sub2(t, bp));
    uint64_t d2 = sub2(p, bp);
    C = add2(C, add2(e, add2(d1, d2)));
    S = t;
}

// Scalar compensated helpers for row norms (identical rounding since R3)
__device__ __forceinline__ void sq_step(float v, float& s, float& c) {
    float p = __fmul_rn(v, v);
    float e = __fmaf_rn(v, v, -p);
    float t = __fadd_rn(s, p);
    float bp = __fsub_rn(t, s);
    float err = __fadd_rn(__fsub_rn(s, __fsub_rn(t, bp)), __fsub_rn(p, bp));
    c = __fadd_rn(c, __fadd_rn(err, e));
    s = t;
}
__device__ __forceinline__ void cs_merge(float& s, float& c, float s2, float c2) {
    float t = __fadd_rn(s, s2);
    float bp = __fsub_rn(t, s);
    float err = __fadd_rn(__fsub_rn(s, __fsub_rn(t, bp)), __fsub_rn(s2, bp));
    c = __fadd_rn(__fadd_rn(c, c2), err);
    s = t;
}

// ---------------------------------------------------------------------------
// mat tile (verbatim values since R3): row norms + compensated fp32x2 Gram ->
// distance matrix, 32x32 triangular tile per block, writes (m,n) + (n,m).
// ---------------------------------------------------------------------------
__device__ void mat_tile(const float* __restrict__ emb, int z, int tid) {
    __shared__ float As[16][33];
    __shared__ float Bs2[16][34];   // paired: [kk][2*tx + (0|1)] = rows tx, tx+16
    __shared__ float s_sq[64];      // [0:32)=A rows, [32:64)=B rows

    int bj = (int)((sqrtf(8.0f * (float)z + 1.0f) - 1.0f) * 0.5f);
    while ((bj + 1) * (bj + 2) / 2 <= z) bj++;
    while (bj * (bj + 1) / 2 > z) bj--;
    int bi = z - bj * (bj + 1) / 2;

    int m0 = bi * 32, n0 = bj * 32;
    int warp = tid >> 5, lane = tid & 31;
    int tx = tid & 15, ty = tid >> 4;

    #pragma unroll
    for (int r = 0; r < 8; r++) {
        int rl = warp * 8 + r;                       // 0..63
        int grow = (rl < 32) ? (m0 + rl) : (n0 + rl - 32);
        const float4* r4 = (const float4*)(emb + grow * DD);
        float4 x = r4[lane];
        float4 y = r4[lane + 32];
        float s = 0.0f, c = 0.0f;
        sq_step(x.x, s, c); sq_step(x.y, s, c); sq_step(x.z, s, c); sq_step(x.w, s, c);
        sq_step(y.x, s, c); sq_step(y.y, s, c); sq_step(y.z, s, c); sq_step(y.w, s, c);
        #pragma unroll
        for (int off = 16; off > 0; off >>= 1) {
            float s2 = __shfl_xor_sync(0xffffffffu, s, off);
            float c2 = __shfl_xor_sync(0xffffffffu, c, off);
            cs_merge(s, c, s2, c2);
        }
        if (lane == 0) s_sq[rl] = __fadd_rn(s, c);
    }
    __syncthreads();

    uint64_t S0 = 0, C0 = 0, S1 = 0, C1 = 0;

    for (int k0 = 0; k0 < DD; k0 += 16) {
        #pragma unroll
        for (int q = 0; q < 2; q++) {
            int idx = tid + q * 256;
            int r = idx >> 4, kk = idx & 15;
            As[kk][r] = emb[(m0 + r) * DD + k0 + kk];
            Bs2[kk][((r & 15) << 1) | (r >> 4)] = emb[(n0 + r) * DD + k0 + kk];
        }
        __syncthreads();
        #pragma unroll
        for (int kk = 0; kk < 16; kk++) {
            uint64_t b2 = *(const uint64_t*)&Bs2[kk][2 * tx];   // rows (tx, tx+16)
            float a0 = As[kk][ty];
            float a1 = As[kk][ty + 16];
            dot2_step(pk2(a0, a0), b2, S0, C0);
            dot2_step(pk2(a1, a1), b2, S1, C1);
        }
        __syncthreads();
    }

    float d00, d01, d10, d11;
    upk2(add2(S0, C0), d00, d01);
    upk2(add2(S1, C1), d10, d11);

    float dots[2][2] = {{d00, d01}, {d10, d11}};
    #pragma unroll
    for (int i = 0; i < 2; i++) {
        int ml = ty + 16 * i;
        int m = m0 + ml;
        float sm = s_sq[ml];
        #pragma unroll
        for (int j = 0; j < 2; j++) {
            int nl = tx + 16 * j;
            int n = n0 + nl;
            // ref order: (sq[a] + sq[n]) - 2*dot, then clamp — no FMA fusion
            float v = fmaxf(__fsub_rn(__fadd_rn(sm, s_sq[32 + nl]),
                                      __fmul_rn(2.0f, dots[i][j])), 0.0f);
            g_mat[m * NN + n] = v;
            g_mat[n * NN + m] = v;
        }
    }
}

// ---------------------------------------------------------------------------
// Tiny pre-kernel: reset the dependency counter (off the hot path).
// ---------------------------------------------------------------------------
__global__ void reset_kernel() {
    if (threadIdx.x == 0) g_done = 0u;
}

// ---------------------------------------------------------------------------
// Fused kernel:
//   blocks [0, 136): mat tile -> fence -> g_done++ -> spin until all 136 done
//     (only mat blocks ever wait, and only on each other; all are wave-1
//     resident and finish within a few us of each other -> deadlock-free,
//     near-zero spin) -> each block writes the valid rows for anchors
//     {bid, bid+136, bid+272, bid+408}, overlapped with the zero stream.
//   blocks [136, 4232): zero-fill invalid rows (verbatim R13, no sync).
// ---------------------------------------------------------------------------
__global__ void __launch_bounds__(256) kernelA(const float* __restrict__ emb,
                                               const int* __restrict__ lw,
                                               float4* __restrict__ out) {
    int tid = threadIdx.x;

    if (blockIdx.x < NMAT) {
        mat_tile(emb, blockIdx.x, tid);
        __syncthreads();
        if (tid == 0) {
            __threadfence();
            atomicAdd(&g_done, 1u);
            while (*(volatile unsigned*)&g_done < NMAT) __nanosleep(32);
        }
        __syncthreads();
        __threadfence();    // acquire: order g_mat reads after counter

        // ---- valid-row epilogue (compacted kernelB body, values verbatim) --
        __shared__ __align__(16) float s_key[NN];
        __shared__ int   s_plist[128];
        __shared__ float s_pval[128];
        __shared__ int s_cnt;
        __shared__ int s_not64;

        if (tid == 0) s_not64 = 0;
        __syncthreads();
        // Probe words [1,3,...,511]: within 2KB, valid for both label layouts.
        if (lw[2 * tid + 1] != 0) s_not64 = 1;
        __syncthreads();
        bool is64 = (s_not64 == 0);

        const float INF = __int_as_float(0x7f800000);
        int warp = tid >> 5, lane = tid & 31;
        const float4* k4 = (const float4*)s_key;

        #pragma unroll
        for (int j = 0; j < 4; j++) {
            int a = blockIdx.x + j * NMAT;
            if (a >= NN) break;

            if (tid == 0) s_cnt = 0;
            __syncthreads();

            int la = is64 ? lw[2 * a] : lw[a];
            #pragma unroll
            for (int rr = 0; rr < 2; rr++) {
                int n = tid + rr * 256;
                float m = __ldcg(&g_mat[a * NN + n]);   // mostly L2 (just written)
                int ln = is64 ? lw[2 * n] : lw[n];
                bool same = (ln == la);
                s_key[n] = same ? INF : m;              // diffs gate
                if (same && n != a) {                   // sames gate -> compact
                    int ix = atomicAdd(&s_cnt, 1);
                    s_plist[ix] = n;
                    s_pval[ix] = m;
                }
            }
            __syncthreads();

            int cnt = s_cnt;
            for (int i = warp; i < cnt; i += 8) {
                int p = s_plist[i];
                float t = s_pval[i];                    // same float as always
                float4* orow = out + ((size_t)a * NN + p) * (NN / 4);
                #pragma unroll
                for (int q = 0; q < 4; q++) {
                    float4 f = k4[q * 32 + lane];
                    float4 r;
                    // ref: (mat[a,n] - mat[a,p]) <= MARGIN, fp32, no fusion.
                    r.x = (__fsub_rn(f.x, t) <= MARGIN) ? 1.0f : 0.0f;
                    r.y = (__fsub_rn(f.y, t) <= MARGIN) ? 1.0f : 0.0f;
                    r.z = (__fsub_rn(f.z, t) <= MARGIN) ? 1.0f : 0.0f;
                    r.w = (__fsub_rn(f.w, t) <= MARGIN) ? 1.0f : 0.0f;
                    __stcs(&orow[q * 32 + lane], r);
                }
            }
            __syncthreads();   // before s_key/s_plist reuse
        }
        return;
    }

    // ---- zero-fill path (verbatim R13, no synchronization) ----
    __shared__ int s_not64z;
    int zb = blockIdx.x - NMAT;          // 0..4095
    int a = zb >> 3;                     // 8 blocks per anchor
    int p0 = (zb & 7) << 6;              // 64-row chunk

    if (tid == 0) s_not64z = 0;
    __syncthreads();
    if (lw[2 * tid + 1] != 0) s_not64z = 1;
    __syncthreads();
    bool is64 = (s_not64z == 0);
    int la = is64 ? lw[2 * a] : lw[a];

    int warp = tid >> 5, lane = tid & 31;
    float4 zv = make_float4(0.0f, 0.0f, 0.0f, 0.0f);

    #pragma unroll
    for (int i = 0; i < 8; i++) {
        int p = p0 + warp * 8 + i;
        int lp = is64 ? lw[2 * p] : lw[p];
        bool valid = (lp == la) && (p != a);
        if (!valid) {
            float4* orow = out + ((size_t)a * NN + p) * (NN / 4);
            #pragma unroll
            for (int q = 0; q < 4; q++)
                __stcs(&orow[q * 32 + lane], zv);
        }
    }
}

// ---------------------------------------------------------------------------
extern "C" void kernel_launch(void* const* d_in, const int* in_sizes, int n_in,
                              void* d_out, int out_size) {
    const float* emb = (const float*)d_in[0];
    const int* labels = (const int*)d_in[1];
    (void)in_sizes; (void)n_in; (void)out_size;

    reset_kernel<<<1, 32>>>();
    kernelA<<<NBLK, 256>>>(emb, labels, (float4*)d_out);
}

// round 17
// speedup vs baseline: 1.0361x; 1.0332x over previous
#include <cuda_runtime.h>
#include <cstdint>

#define NN 512
#define DD 256
#define MARGIN 0.2f
#define NMAT 136          // triangular 32x32 tiles
#define NZERO 4096        // zero-fill chunks total (64 rows each)
#define NZ_A 3584         // zero chunks in kernelA (anchors 0..447)
#define NZ_B (NZERO - NZ_A)   // 512 zero chunks in kernelB (anchors 448..511)

// Scratch (device global, no allocation)
__device__ float g_mat[NN * NN];

// ---------------------------------------------------------------------------
// Packed f32x2 helpers (Blackwell). Negation via exact *-1 / fma preserves
// the TwoSum algebra.
// ---------------------------------------------------------------------------
__device__ __forceinline__ uint64_t pk2(float lo, float hi) {
    uint64_t d; asm("mov.b64 %0, {%1,%2};" : "=l"(d) : "f"(lo), "f"(hi)); return d;
}
__device__ __forceinline__ void upk2(uint64_t v, float& lo, float& hi) {
    asm("mov.b64 {%0,%1}, %2;" : "=f"(lo), "=f"(hi) : "l"(v));
}
__device__ __forceinline__ uint64_t mul2(uint64_t a, uint64_t b) {
    uint64_t d; asm("mul.rn.f32x2 %0, %1, %2;" : "=l"(d) : "l"(a), "l"(b)); return d;
}
__device__ __forceinline__ uint64_t add2(uint64_t a, uint64_t b) {
    uint64_t d; asm("add.rn.f32x2 %0, %1, %2;" : "=l"(d) : "l"(a), "l"(b)); return d;
}
__device__ __forceinline__ uint64_t fma2(uint64_t a, uint64_t b, uint64_t c) {
    uint64_t d; asm("fma.rn.f32x2 %0, %1, %2, %3;" : "=l"(d) : "l"(a), "l"(b), "l"(c)); return d;
}
#define NEG1_2 0xBF800000BF800000ULL
__device__ __forceinline__ uint64_t neg2(uint64_t x) { return mul2(x, NEG1_2); }
__device__ __forceinline__ uint64_t sub2(uint64_t a, uint64_t b) { return fma2(b, NEG1_2, a); }

// Compensated accumulate of product a*b into (S, C): Dot2 (Ogita-Rump-Oishi).
__device__ __forceinline__ void dot2_step(uint64_t a, uint64_t b,
                                          uint64_t& S, uint64_t& C) {
    uint64_t p  = mul2(a, b);
    uint64_t e  = fma2(a, b, neg2(p));   // exact product error
    uint64_t t  = add2(S, p);            // TwoSum(S, p)
    uint64_t bp = sub2(t, S);
    uint64_t d1 = sub2(S, sub2(t, bp));
    uint64_t d2 = sub2(p, bp);
    C = add2(C, add2(e, add2(d1, d2)));
    S = t;
}

// Scalar compensated helpers for row norms (identical rounding since R3)
__device__ __forceinline__ void sq_step(float v, float& s, float& c) {
    float p = __fmul_rn(v, v);
    float e = __fmaf_rn(v, v, -p);
    float t = __fadd_rn(s, p);
    float bp = __fsub_rn(t, s);
    float err = __fadd_rn(__fsub_rn(s, __fsub_rn(t, bp)), __fsub_rn(p, bp));
    c = __fadd_rn(c, __fadd_rn(err, e));
    s = t;
}
__device__ __forceinline__ void cs_merge(float& s, float& c, float s2, float c2) {
    float t = __fadd_rn(s, s2);
    float bp = __fsub_rn(t, s);
    float err = __fadd_rn(__fsub_rn(s, __fsub_rn(t, bp)), __fsub_rn(s2, bp));
    c = __fadd_rn(__fadd_rn(c, c2), err);
    s = t;
}

// ---------------------------------------------------------------------------
// mat tile (verbatim values since R3): row norms + compensated fp32x2 Gram ->
// distance matrix, 32x32 triangular tile per block, writes (m,n) + (n,m).
// ---------------------------------------------------------------------------
__device__ void mat_tile(const float* __restrict__ emb, int z, int tid) {
    __shared__ float As[16][33];
    __shared__ float Bs2[16][34];   // paired: [kk][2*tx + (0|1)] = rows tx, tx+16
    __shared__ float s_sq[64];      // [0:32)=A rows, [32:64)=B rows

    int bj = (int)((sqrtf(8.0f * (float)z + 1.0f) - 1.0f) * 0.5f);
    while ((bj + 1) * (bj + 2) / 2 <= z) bj++;
    while (bj * (bj + 1) / 2 > z) bj--;
    int bi = z - bj * (bj + 1) / 2;

    int m0 = bi * 32, n0 = bj * 32;
    int warp = tid >> 5, lane = tid & 31;
    int tx = tid & 15, ty = tid >> 4;

    #pragma unroll
    for (int r = 0; r < 8; r++) {
        int rl = warp * 8 + r;                       // 0..63
        int grow = (rl < 32) ? (m0 + rl) : (n0 + rl - 32);
        const float4* r4 = (const float4*)(emb + grow * DD);
        float4 x = r4[lane];
        float4 y = r4[lane + 32];
        float s = 0.0f, c = 0.0f;
        sq_step(x.x, s, c); sq_step(x.y, s, c); sq_step(x.z, s, c); sq_step(x.w, s, c);
        sq_step(y.x, s, c); sq_step(y.y, s, c); sq_step(y.z, s, c); sq_step(y.w, s, c);
        #pragma unroll
        for (int off = 16; off > 0; off >>= 1) {
            float s2 = __shfl_xor_sync(0xffffffffu, s, off);
            float c2 = __shfl_xor_sync(0xffffffffu, c, off);
            cs_merge(s, c, s2, c2);
        }
        if (lane == 0) s_sq[rl] = __fadd_rn(s, c);
    }
    __syncthreads();

    uint64_t S0 = 0, C0 = 0, S1 = 0, C1 = 0;

    for (int k0 = 0; k0 < DD; k0 += 16) {
        #pragma unroll
        for (int q = 0; q < 2; q++) {
            int idx = tid + q * 256;
            int r = idx >> 4, kk = idx & 15;
            As[kk][r] = emb[(m0 + r) * DD + k0 + kk];
            Bs2[kk][((r & 15) << 1) | (r >> 4)] = emb[(n0 + r) * DD + k0 + kk];
        }
        __syncthreads();
        #pragma unroll
        for (int kk = 0; kk < 16; kk++) {
            uint64_t b2 = *(const uint64_t*)&Bs2[kk][2 * tx];   // rows (tx, tx+16)
            float a0 = As[kk][ty];
            float a1 = As[kk][ty + 16];
            dot2_step(pk2(a0, a0), b2, S0, C0);
            dot2_step(pk2(a1, a1), b2, S1, C1);
        }
        __syncthreads();
    }

    float d00, d01, d10, d11;
    upk2(add2(S0, C0), d00, d01);
    upk2(add2(S1, C1), d10, d11);

    float dots[2][2] = {{d00, d01}, {d10, d11}};
    #pragma unroll
    for (int i = 0; i < 2; i++) {
        int ml = ty + 16 * i;
        int m = m0 + ml;
        float sm = s_sq[ml];
        #pragma unroll
        for (int j = 0; j < 2; j++) {
            int nl = tx + 16 * j;
            int n = n0 + nl;
            // ref order: (sq[a] + sq[n]) - 2*dot, then clamp — no FMA fusion
            float v = fmaxf(__fsub_rn(__fadd_rn(sm, s_sq[32 + nl]),
                                      __fmul_rn(2.0f, dots[i][j])), 0.0f);
            g_mat[m * NN + n] = v;
            g_mat[n * NN + m] = v;
        }
    }
}

// ---------------------------------------------------------------------------
// zero chunk (verbatim R13 zero path): zero-fill the invalid (a,p) rows of a
// 64-row chunk.
// ---------------------------------------------------------------------------
__device__ __forceinline__ void zero_chunk(const int* __restrict__ lw,
                                           float4* __restrict__ out,
                                           int zb, int tid) {
    __shared__ int s_not64z;
    int a = zb >> 3;                     // 8 chunks per anchor
    int p0 = (zb & 7) << 6;              // 64-row chunk

    if (tid == 0) s_not64z = 0;
    __syncthreads();
    // Probe words [1,3,...,511]: within 2KB, valid for both label layouts.
    if (lw[2 * tid + 1] != 0) s_not64z = 1;
    __syncthreads();
    bool is64 = (s_not64z == 0);
    int la = is64 ? lw[2 * a] : lw[a];

    int warp = tid >> 5, lane = tid & 31;
    float4 zv = make_float4(0.0f, 0.0f, 0.0f, 0.0f);

    #pragma unroll
    for (int i = 0; i < 8; i++) {
        int p = p0 + warp * 8 + i;
        int lp = is64 ? lw[2 * p] : lw[p];
        bool valid = (lp == la) && (p != a);
        if (!valid) {
            float4* orow = out + ((size_t)a * NN + p) * (NN / 4);
            #pragma unroll
            for (int q = 0; q < 4; q++)
                __stcs(&orow[q * 32 + lane], zv);
        }
    }
}

// ---------------------------------------------------------------------------
// Kernel A (R13 structure): blocks [0,136) compute the distance matrix;
// blocks [136, 136+3584) zero-fill invalid rows of anchors 0..447 (~434MB).
// The Gram compute hides under the store stream.
// ---------------------------------------------------------------------------
__global__ void __launch_bounds__(256) kernelA(const float* __restrict__ emb,
                                               const int* __restrict__ lw,
                                               float4* __restrict__ out) {
    int tid = threadIdx.x;
    if (blockIdx.x < NMAT) {
        mat_tile(emb, blockIdx.x, tid);
        return;
    }
    zero_chunk(lw, out, blockIdx.x - NMAT, tid);
}

// ---------------------------------------------------------------------------
// Kernel B: fills its fixed ~10us boundary window with useful stores.
//   blocks [0, 512):    zero chunks for anchors 448..511 (~62MB)
//   blocks [512, 1024): valid-row blocks, one per anchor (R13 compact body,
//                       values bit-identical)
// Total ~78MB of stores — if the post-kernelA window was idle-floor, these
// hide inside it.
// ---------------------------------------------------------------------------
__global__ void __launch_bounds__(256) kernelB(const int* __restrict__ lw,
                                               float4* __restrict__ out) {
    int tid = threadIdx.x;

    if (blockIdx.x < NZ_B) {
        zero_chunk(lw, out, NZ_A + blockIdx.x, tid);
        return;
    }

    // ---- valid-row path (verbatim R13 kernelB body) ----
    __shared__ __align__(16) float s_key[NN];
    __shared__ int   s_plist[128];
    __shared__ float s_pval[128];
    __shared__ int s_cnt;
    __shared__ int s_not64;

    int a = blockIdx.x - NZ_B;

    if (tid == 0) { s_not64 = 0; s_cnt = 0; }
    __syncthreads();
    // Probe words [1,3,...,511]: within 2KB, valid for both label layouts.
    if (lw[2 * tid + 1] != 0) s_not64 = 1;
    __syncthreads();
    bool is64 = (s_not64 == 0);
    int la = is64 ? lw[2 * a] : lw[a];

    const float INF = __int_as_float(0x7f800000);
    #pragma unroll
    for (int rr = 0; rr < 2; rr++) {
        int n = tid + rr * 256;
        float m = __ldcg(&g_mat[a * NN + n]);
        int ln = is64 ? lw[2 * n] : lw[n];
        bool same = (ln == la);
        s_key[n] = same ? INF : m;                    // diffs gate
        if (same && n != a) {                         // sames gate -> compact
            int ix = atomicAdd(&s_cnt, 1);
            s_plist[ix] = n;
            s_pval[ix] = m;
        }
    }
    __syncthreads();

    int cnt = s_cnt;
    int warp = tid >> 5, lane = tid & 31;
    const float4* k4 = (const float4*)s_key;

    for (int i = warp; i < cnt; i += 8) {
        int p = s_plist[i];
        float t = s_pval[i];                          // same float as always
        float4* orow = out + ((size_t)a * NN + p) * (NN / 4);
        #pragma unroll
        for (int q = 0; q < 4; q++) {
            float4 f = k4[q * 32 + lane];
            float4 r;
            // ref: (mat[a,n] - mat[a,p]) <= MARGIN, fp32, no fusion.
            r.x = (__fsub_rn(f.x, t) <= MARGIN) ? 1.0f : 0.0f;
            r.y = (__fsub_rn(f.y, t) <= MARGIN) ? 1.0f : 0.0f;
            r.z = (__fsub_rn(f.z, t) <= MARGIN) ? 1.0f : 0.0f;
            r.w = (__fsub_rn(f.w, t) <= MARGIN) ? 1.0f : 0.0f;
            __stcs(&orow[q * 32 + lane], r);
        }
    }
}

// ---------------------------------------------------------------------------
extern "C" void kernel_launch(void* const* d_in, const int* in_sizes, int n_in,
                              void* d_out, int out_size) {
    const float* emb = (const float*)d_in[0];
    const int* labels = (const int*)d_in[1];
    (void)in_sizes; (void)n_in; (void)out_size;

    kernelA<<<NMAT + NZ_A, 256>>>(emb, labels, (float4*)d_out);
    kernelB<<<NZ_B + NN, 256>>>(labels, (float4*)d_out);
}